// round 14
// baseline (speedup 1.0000x reference)
#include <cuda_runtime.h>
#include <cuda_fp16.h>
#include <cstdint>

#define KTAPS 27
#define C 32
#define NB 8
#define TILE_M 256
#define THREADS 256
#define GEPS 1e-5f
#define MAXN 300032

// ---- dynamic SMEM layout (deconv) ----
#define OFF_WF  0                   // 27*4*32*16 = 55296 (fragment-ordered W, fp16)
#define OFF_NG  55296               // 256*27*4 = 27648 (neighbor indices)
#define SMEM_TOTAL 82944

// ---- device-global scratch / accumulators ----
__device__ __half g_hdata[(size_t)MAXN * C];   // K-permuted fp16 copy of data
__device__ __align__(16) float g_sum[NB * C];
__device__ __align__(16) float g_sumsq[NB * C];
__device__ float g_cnt[NB];
__device__ unsigned int g_arrive;

// ===================== helpers =====================
__device__ __forceinline__ void mma16(float c[4], uint32_t a0, uint32_t a1,
                                      uint32_t a2, uint32_t a3,
                                      uint32_t b0, uint32_t b1) {
    asm volatile("mma.sync.aligned.m16n8k16.row.col.f32.f16.f16.f32 "
        "{%0,%1,%2,%3}, {%4,%5,%6,%7}, {%8,%9}, {%0,%1,%2,%3};"
        : "+f"(c[0]), "+f"(c[1]), "+f"(c[2]), "+f"(c[3])
        : "r"(a0), "r"(a1), "r"(a2), "r"(a3), "r"(b0), "r"(b1));
}
__device__ __forceinline__ uint32_t pack_h2(float lo, float hi) {
    __half2 h = __floats2half2_rn(lo, hi);
    return *reinterpret_cast<uint32_t*>(&h);
}
// logical channel at phys slot p:  p = 8q + 4g + jj -> L = 16g + 2q + 8*(jj>>1) + (jj&1)
__device__ __forceinline__ int phys2log(int p) {
    int q = p >> 3, g = (p >> 2) & 1, jj = p & 3;
    return g * 16 + 2 * q + 8 * (jj >> 1) + (jj & 1);
}

// ===================== kernels =====================
// Pre-convert data -> fp16 (K-permuted); block 0 zeroes the stat accumulators
// and the grid-barrier counter (runs before every consumer, incl. on replays).
__global__ void convert_kernel(const float* __restrict__ data, int n_nodes) {
    if (blockIdx.x == 0) {
        int t = threadIdx.x;
        if (t < NB * C) { g_sum[t] = 0.f; g_sumsq[t] = 0.f; }
        if (t < NB) g_cnt[t] = 0.f;
        if (t == 0) g_arrive = 0u;
    }
    int idx = blockIdx.x * blockDim.x + threadIdx.x;
    if (idx >= n_nodes * C) return;
    int n = idx >> 5, p = idx & 31;
    g_hdata[idx] = __float2half_rn(data[(n << 5) + phys2log(p)]);
}

// Persistent deconv: fp16 m16n8k16 (validated R11 form, byte-identical).
__global__ void __launch_bounds__(THREADS, 2)
deconv_kernel(const float* __restrict__ weights,
              const int*   __restrict__ neigh,
              float*       __restrict__ h_out,
              int n_nodes, int n_tiles)
{
    extern __shared__ __align__(16) char smem[];
    const int tid = threadIdx.x;
    const int warp = tid >> 5;
    const int lane = tid & 31;
    const int q = lane & 3;
    const int rbase = lane >> 2;

    // Build fragment-ordered W table.
    for (int e = tid; e < KTAPS * 4 * 32; e += THREADS) {
        int k = e >> 7, rem = e & 127;
        int gn = rem >> 5, l = rem & 31;
        int cc = l & 3, rr = l >> 2;
        int n = gn * 8 + rr;
        uint4 f;
        uint32_t* fc = reinterpret_cast<uint32_t*>(&f);
#pragma unroll
        for (int j = 0; j < 4; j++) {
            int g = j >> 1, hb = j & 1;
            int kl = g * 16 + 2 * cc + 8 * hb;
            fc[j] = pack_h2(weights[(k * 32 + kl) * 32 + n],
                            weights[(k * 32 + kl + 1) * 32 + n]);
        }
        *reinterpret_cast<uint4*>(smem + OFF_WF + e * 16) = f;
    }
    __syncthreads();

#define LOAD_A(buf, kk) do { \
    _Pragma("unroll") \
    for (int mb = 0; mb < 2; mb++) { \
        int lr0 = warp * 32 + mb * 16 + rbase; \
        int nb0 = 0, nb1 = 0; \
        if (lr0 < nvalid)     nb0 = *(const int*)(smem + OFF_NG + (lr0 * KTAPS + (kk)) * 4); \
        if (lr0 + 8 < nvalid) nb1 = *(const int*)(smem + OFF_NG + ((lr0 + 8) * KTAPS + (kk)) * 4); \
        fAr[buf][mb * 2 + 0] = reinterpret_cast<const uint4*>(g_hdata + ((size_t)nb0 << 5))[q]; \
        fAr[buf][mb * 2 + 1] = reinterpret_cast<const uint4*>(g_hdata + ((size_t)nb1 << 5))[q]; \
    } \
} while (0)

    for (int tile = blockIdx.x; tile < n_tiles; tile += gridDim.x) {
        const int base = tile * TILE_M;
        const int nvalid = min(TILE_M, n_nodes - base);

        __syncthreads();
        for (int idx = tid; idx < nvalid * KTAPS; idx += THREADS)
            *(int*)(smem + OFF_NG + idx * 4) = neigh[(size_t)base * KTAPS + idx];
        __syncthreads();

        float acc[2][4][4];
#pragma unroll
        for (int mb = 0; mb < 2; mb++)
#pragma unroll
            for (int gn = 0; gn < 4; gn++)
#pragma unroll
                for (int p = 0; p < 4; p++) acc[mb][gn][p] = 0.f;

        uint4 fAr[2][4];
        LOAD_A(0, 0);

#pragma unroll
        for (int k = 0; k < KTAPS; k++) {
            const int cur = k & 1;
            if (k + 1 < KTAPS) LOAD_A((k + 1) & 1, k + 1);

            const char* wf = smem + OFF_WF + (size_t)(k * 4) * 512;
#pragma unroll
            for (int gn = 0; gn < 4; gn++) {
                uint4 Bf = *reinterpret_cast<const uint4*>(wf + gn * 512 + lane * 16);
#pragma unroll
                for (int mb = 0; mb < 2; mb++) {
                    const uint4 U0 = fAr[cur][mb * 2 + 0];
                    const uint4 U1 = fAr[cur][mb * 2 + 1];
                    mma16(acc[mb][gn], U0.x, U1.x, U0.y, U1.y, Bf.x, Bf.y);
                    mma16(acc[mb][gn], U0.z, U1.z, U0.w, U1.w, Bf.z, Bf.w);
                }
            }
        }

#pragma unroll
        for (int mb = 0; mb < 2; mb++) {
            const int r0 = base + warp * 32 + mb * 16 + (lane >> 2);
            const int r1 = r0 + 8;
#pragma unroll
            for (int gn = 0; gn < 4; gn++) {
                const int cc = gn * 8 + 2 * (lane & 3);
                if (r0 < n_nodes)
                    *(float2*)(h_out + (size_t)r0 * C + cc) =
                        make_float2(acc[mb][gn][0], acc[mb][gn][1]);
                if (r1 < n_nodes)
                    *(float2*)(h_out + (size_t)r1 * C + cc) =
                        make_float2(acc[mb][gn][2], acc[mb][gn][3]);
            }
        }
    }
#undef LOAD_A
}

// Fused stats + norm + relu: persistent 296-block kernel with a software
// grid barrier between the reduction phase and the normalize phase.
// Phase-1 segment body is the validated R11 reduction (run state reset per
// segment). Phase 2 computes per-(batch,group) mean/istd inline (R13 form)
// and applies gn+relu via a grid-stride float4 loop (h is L2-hot).
#define SNB 512
#define SGRID 296
__global__ void __launch_bounds__(SNB, 2)
stats_norm_kernel(float* __restrict__ h,
                  const int* __restrict__ batch_id,
                  const float* __restrict__ gamma,
                  const float* __restrict__ beta,
                  int n_nodes)
{
    __shared__ float sum_s[NB * C], sq_s[NB * C], cnt_s[NB];
    __shared__ int batch_s[SNB];
    __shared__ float mean_s[NB * 8], istd_s[NB * 8];
    const int tid = threadIdx.x, w = tid >> 5, lane = tid & 31;
    const int rs = lane >> 3;          // row slot 0..3
    const int cg = lane & 7;           // 4-channel group
    if (tid < NB * C) { sum_s[tid] = 0.f; sq_s[tid] = 0.f; }
    if (tid < NB) cnt_s[tid] = 0.f;

    const int nsegs = (n_nodes + SGRID * SNB - 1) / (SGRID * SNB);
    for (int seg = 0; seg < nsegs; seg++) {
        const int base = (seg * SGRID + blockIdx.x) * SNB;
        const int nvalid = min(SNB, n_nodes - base);   // may be <= 0
        __syncthreads();                               // protect batch_s reuse
        if (tid < nvalid) batch_s[tid] = batch_id[base + tid];
        __syncthreads();
        if (tid < nvalid) atomicAdd(&cnt_s[batch_s[tid]], 1.0f);

        const int row0 = w * 32 + rs * 8;
        float4 ls = make_float4(0.f, 0.f, 0.f, 0.f);
        float4 lq = make_float4(0.f, 0.f, 0.f, 0.f);
        int curb = -1;
#pragma unroll
        for (int j = 0; j < 8; j++) {
            const int r = row0 + j;
            if (r < nvalid) {
                const int b = batch_s[r];
                if (b != curb) {
                    if (curb >= 0) {
                        float* su = &sum_s[curb * C + cg * 4];
                        float* sq = &sq_s[curb * C + cg * 4];
                        atomicAdd(su + 0, ls.x); atomicAdd(su + 1, ls.y);
                        atomicAdd(su + 2, ls.z); atomicAdd(su + 3, ls.w);
                        atomicAdd(sq + 0, lq.x); atomicAdd(sq + 1, lq.y);
                        atomicAdd(sq + 2, lq.z); atomicAdd(sq + 3, lq.w);
                        ls = make_float4(0.f, 0.f, 0.f, 0.f);
                        lq = make_float4(0.f, 0.f, 0.f, 0.f);
                    }
                    curb = b;
                }
                float4 v = *reinterpret_cast<const float4*>(h + (size_t)(base + r) * C + cg * 4);
                ls.x += v.x; lq.x = fmaf(v.x, v.x, lq.x);
                ls.y += v.y; lq.y = fmaf(v.y, v.y, lq.y);
                ls.z += v.z; lq.z = fmaf(v.z, v.z, lq.z);
                ls.w += v.w; lq.w = fmaf(v.w, v.w, lq.w);
            }
        }
        {
            const int curb0 = __shfl_sync(0xffffffffu, curb, 0);
            const bool uniform = __all_sync(0xffffffffu, curb == curb0) && (curb0 >= 0);
            if (uniform) {
#pragma unroll
                for (int off = 8; off <= 16; off <<= 1) {
                    ls.x += __shfl_xor_sync(0xffffffffu, ls.x, off);
                    ls.y += __shfl_xor_sync(0xffffffffu, ls.y, off);
                    ls.z += __shfl_xor_sync(0xffffffffu, ls.z, off);
                    ls.w += __shfl_xor_sync(0xffffffffu, ls.w, off);
                    lq.x += __shfl_xor_sync(0xffffffffu, lq.x, off);
                    lq.y += __shfl_xor_sync(0xffffffffu, lq.y, off);
                    lq.z += __shfl_xor_sync(0xffffffffu, lq.z, off);
                    lq.w += __shfl_xor_sync(0xffffffffu, lq.w, off);
                }
                if (rs == 0) {
                    float* su = &sum_s[curb0 * C + cg * 4];
                    float* sq = &sq_s[curb0 * C + cg * 4];
                    atomicAdd(su + 0, ls.x); atomicAdd(su + 1, ls.y);
                    atomicAdd(su + 2, ls.z); atomicAdd(su + 3, ls.w);
                    atomicAdd(sq + 0, lq.x); atomicAdd(sq + 1, lq.y);
                    atomicAdd(sq + 2, lq.z); atomicAdd(sq + 3, lq.w);
                }
            } else if (curb >= 0) {
                float* su = &sum_s[curb * C + cg * 4];
                float* sq = &sq_s[curb * C + cg * 4];
                atomicAdd(su + 0, ls.x); atomicAdd(su + 1, ls.y);
                atomicAdd(su + 2, ls.z); atomicAdd(su + 3, ls.w);
                atomicAdd(sq + 0, lq.x); atomicAdd(sq + 1, lq.y);
                atomicAdd(sq + 2, lq.z); atomicAdd(sq + 3, lq.w);
            }
        }
    }
    __syncthreads();
    if (tid < NB * C) {
        atomicAdd(&g_sum[tid], sum_s[tid]);
        atomicAdd(&g_sumsq[tid], sq_s[tid]);
    }
    if (tid < NB) atomicAdd(&g_cnt[tid], cnt_s[tid]);

    // ---- software grid barrier ----
    __threadfence();
    __syncthreads();
    if (tid == 0) {
        atomicAdd(&g_arrive, 1u);
        while (atomicAdd(&g_arrive, 0u) < (unsigned)gridDim.x) {
            __nanosleep(200);
        }
    }
    __syncthreads();

    // ---- phase 2: inline GN stats + normalize + relu ----
    if (tid < NB * 8) {               // t = b*8 + g (group == float4 slot, C/G=4)
        const int b = tid >> 3;
        const float cnt = g_cnt[b];
        const float inv_cnt = 1.f / (cnt * 4.f + GEPS);
        float4 su = reinterpret_cast<const float4*>(g_sum)[tid];
        float4 qq = reinterpret_cast<const float4*>(g_sumsq)[tid];
        const float s = su.x + su.y + su.z + su.w;
        const float q = qq.x + qq.y + qq.z + qq.w;
        const float mean = s * inv_cnt;
        const float var  = (q - 2.f * mean * s + 4.f * cnt * mean * mean) * inv_cnt;
        mean_s[tid] = mean;
        istd_s[tid] = rsqrtf(var + GEPS);
    }
    __syncthreads();

    const int total = n_nodes * (C / 4);
    const int stride = SGRID * SNB;
    for (int idx = blockIdx.x * SNB + tid; idx < total; idx += stride) {
        int n = idx >> 3, s = idx & 7;
        int b = batch_id[n];
        const float mean = mean_s[b * 8 + s];
        const float istd = istd_s[b * 8 + s];
        float4 g4 = reinterpret_cast<const float4*>(gamma)[s];
        float4 b4 = reinterpret_cast<const float4*>(beta)[s];
        float4 hv = reinterpret_cast<float4*>(h)[idx];
        float4 o;
        o.x = fmaxf(fmaf(hv.x - mean, istd * g4.x, b4.x), 0.f);
        o.y = fmaxf(fmaf(hv.y - mean, istd * g4.y, b4.y), 0.f);
        o.z = fmaxf(fmaf(hv.z - mean, istd * g4.z, b4.z), 0.f);
        o.w = fmaxf(fmaf(hv.w - mean, istd * g4.w, b4.w), 0.f);
        reinterpret_cast<float4*>(h)[idx] = o;
    }
}

// ===================== launch =====================
extern "C" void kernel_launch(void* const* d_in, const int* in_sizes, int n_in,
                              void* d_out, int out_size)
{
    const float* data     = (const float*)d_in[0];
    const float* weights  = (const float*)d_in[1];
    const float* gamma    = (const float*)d_in[2];
    const float* beta     = (const float*)d_in[3];
    const int*   neigh    = (const int*)d_in[4];
    const int*   batch_id = (const int*)d_in[5];
    float* out = (float*)d_out;

    const int n_nodes = in_sizes[0] / C;
    const int n_tiles = (n_nodes + TILE_M - 1) / TILE_M;

    cudaFuncSetAttribute(deconv_kernel,
                         cudaFuncAttributeMaxDynamicSharedMemorySize, SMEM_TOTAL);

    convert_kernel<<<(n_nodes * C + 255) / 256, 256>>>(data, n_nodes);

    int grid = n_tiles < 296 ? n_tiles : 296;   // 2 CTAs/SM
    deconv_kernel<<<grid, THREADS, SMEM_TOTAL>>>(weights, neigh, out,
                                                 n_nodes, n_tiles);

    stats_norm_kernel<<<SGRID, SNB>>>(out, batch_id, gamma, beta, n_nodes);
}

// round 15
// speedup vs baseline: 1.1548x; 1.1548x over previous
#include <cuda_runtime.h>
#include <cuda_fp16.h>
#include <cstdint>

#define KTAPS 27
#define C 32
#define NB 8
#define TILE_M 256
#define THREADS 256
#define GEPS 1e-5f
#define MAXN 300032

// ---- dynamic SMEM layout ----
#define OFF_WF  0                   // 27*4*32*16 = 55296 (fragment-ordered W, fp16)
#define OFF_NG  55296               // 256*27*4 = 27648 (neighbor indices)
#define SMEM_TOTAL 82944

// ---- device-global scratch / accumulators ----
__device__ __half g_hdata[(size_t)MAXN * C];   // K-permuted fp16 copy of data
__device__ __align__(16) float g_sum[NB * C];
__device__ __align__(16) float g_sumsq[NB * C];
__device__ float g_cnt[NB];
__device__ __align__(16) float g_scale[NB * C];
__device__ __align__(16) float g_shift[NB * C];

// ===================== helpers =====================
__device__ __forceinline__ void mma16(float c[4], uint32_t a0, uint32_t a1,
                                      uint32_t a2, uint32_t a3,
                                      uint32_t b0, uint32_t b1) {
    asm volatile("mma.sync.aligned.m16n8k16.row.col.f32.f16.f16.f32 "
        "{%0,%1,%2,%3}, {%4,%5,%6,%7}, {%8,%9}, {%0,%1,%2,%3};"
        : "+f"(c[0]), "+f"(c[1]), "+f"(c[2]), "+f"(c[3])
        : "r"(a0), "r"(a1), "r"(a2), "r"(a3), "r"(b0), "r"(b1));
}
__device__ __forceinline__ uint32_t pack_h2(float lo, float hi) {
    __half2 h = __floats2half2_rn(lo, hi);
    return *reinterpret_cast<uint32_t*>(&h);
}

// ===================== kernels =====================
__global__ void zero_stats_kernel() {
    int t = threadIdx.x;
    if (t < NB * C) { g_sum[t] = 0.f; g_sumsq[t] = 0.f; }
    if (t < NB) g_cnt[t] = 0.f;
}

// Vectorized K-permuted fp16 convert. Thread = (node, quad q): phys slots
// 8q..8q+7 read logical channels {2q,2q+1, 2q+8,2q+9, 2q+16,2q+17, 2q+24,2q+25}
// (4 float2 loads) and write one uint4 (16B) — fully coalesced stores.
__global__ void __launch_bounds__(256)
convert_kernel(const float* __restrict__ data, int n_nodes) {
    int t = blockIdx.x * blockDim.x + threadIdx.x;
    if (t >= n_nodes * 4) return;
    const int n = t >> 2, q = t & 3;
    const float2* src = reinterpret_cast<const float2*>(data + ((size_t)n << 5));
    float2 v0 = src[q];          // L = 2q, 2q+1
    float2 v1 = src[q + 4];      // L = 2q+8, 2q+9
    float2 v2 = src[q + 8];      // L = 2q+16, 2q+17
    float2 v3 = src[q + 12];     // L = 2q+24, 2q+25
    uint4 o;
    o.x = pack_h2(v0.x, v0.y);
    o.y = pack_h2(v1.x, v1.y);
    o.z = pack_h2(v2.x, v2.y);
    o.w = pack_h2(v3.x, v3.y);
    reinterpret_cast<uint4*>(g_hdata + ((size_t)n << 5))[q] = o;
}

// Persistent deconv: fp16 m16n8k16 (validated R11 form, byte-identical).
__global__ void __launch_bounds__(THREADS, 2)
deconv_kernel(const float* __restrict__ weights,
              const int*   __restrict__ neigh,
              float*       __restrict__ h_out,
              int n_nodes, int n_tiles)
{
    extern __shared__ __align__(16) char smem[];
    const int tid = threadIdx.x;
    const int warp = tid >> 5;
    const int lane = tid & 31;
    const int q = lane & 3;
    const int rbase = lane >> 2;

    // Build fragment-ordered W table.
    for (int e = tid; e < KTAPS * 4 * 32; e += THREADS) {
        int k = e >> 7, rem = e & 127;
        int gn = rem >> 5, l = rem & 31;
        int cc = l & 3, rr = l >> 2;
        int n = gn * 8 + rr;
        uint4 f;
        uint32_t* fc = reinterpret_cast<uint32_t*>(&f);
#pragma unroll
        for (int j = 0; j < 4; j++) {
            int g = j >> 1, hb = j & 1;
            int kl = g * 16 + 2 * cc + 8 * hb;
            fc[j] = pack_h2(weights[(k * 32 + kl) * 32 + n],
                            weights[(k * 32 + kl + 1) * 32 + n]);
        }
        *reinterpret_cast<uint4*>(smem + OFF_WF + e * 16) = f;
    }
    __syncthreads();

#define LOAD_A(buf, kk) do { \
    _Pragma("unroll") \
    for (int mb = 0; mb < 2; mb++) { \
        int lr0 = warp * 32 + mb * 16 + rbase; \
        int nb0 = 0, nb1 = 0; \
        if (lr0 < nvalid)     nb0 = *(const int*)(smem + OFF_NG + (lr0 * KTAPS + (kk)) * 4); \
        if (lr0 + 8 < nvalid) nb1 = *(const int*)(smem + OFF_NG + ((lr0 + 8) * KTAPS + (kk)) * 4); \
        fAr[buf][mb * 2 + 0] = reinterpret_cast<const uint4*>(g_hdata + ((size_t)nb0 << 5))[q]; \
        fAr[buf][mb * 2 + 1] = reinterpret_cast<const uint4*>(g_hdata + ((size_t)nb1 << 5))[q]; \
    } \
} while (0)

    for (int tile = blockIdx.x; tile < n_tiles; tile += gridDim.x) {
        const int base = tile * TILE_M;
        const int nvalid = min(TILE_M, n_nodes - base);

        __syncthreads();
        for (int idx = tid; idx < nvalid * KTAPS; idx += THREADS)
            *(int*)(smem + OFF_NG + idx * 4) = neigh[(size_t)base * KTAPS + idx];
        __syncthreads();

        float acc[2][4][4];
#pragma unroll
        for (int mb = 0; mb < 2; mb++)
#pragma unroll
            for (int gn = 0; gn < 4; gn++)
#pragma unroll
                for (int p = 0; p < 4; p++) acc[mb][gn][p] = 0.f;

        uint4 fAr[2][4];
        LOAD_A(0, 0);

#pragma unroll
        for (int k = 0; k < KTAPS; k++) {
            const int cur = k & 1;
            if (k + 1 < KTAPS) LOAD_A((k + 1) & 1, k + 1);

            const char* wf = smem + OFF_WF + (size_t)(k * 4) * 512;
#pragma unroll
            for (int gn = 0; gn < 4; gn++) {
                uint4 Bf = *reinterpret_cast<const uint4*>(wf + gn * 512 + lane * 16);
#pragma unroll
                for (int mb = 0; mb < 2; mb++) {
                    const uint4 U0 = fAr[cur][mb * 2 + 0];
                    const uint4 U1 = fAr[cur][mb * 2 + 1];
                    mma16(acc[mb][gn], U0.x, U1.x, U0.y, U1.y, Bf.x, Bf.y);
                    mma16(acc[mb][gn], U0.z, U1.z, U0.w, U1.w, Bf.z, Bf.w);
                }
            }
        }

#pragma unroll
        for (int mb = 0; mb < 2; mb++) {
            const int r0 = base + warp * 32 + mb * 16 + (lane >> 2);
            const int r1 = r0 + 8;
#pragma unroll
            for (int gn = 0; gn < 4; gn++) {
                const int cc = gn * 8 + 2 * (lane & 3);
                if (r0 < n_nodes)
                    *(float2*)(h_out + (size_t)r0 * C + cc) =
                        make_float2(acc[mb][gn][0], acc[mb][gn][1]);
                if (r1 < n_nodes)
                    *(float2*)(h_out + (size_t)r1 * C + cc) =
                        make_float2(acc[mb][gn][2], acc[mb][gn][3]);
            }
        }
    }
#undef LOAD_A
}

// Vectorized per-(batch,channel) stats (validated R11 form, byte-identical).
#define RNPB 256
__global__ void __launch_bounds__(256)
reduce_stats_kernel(const float* __restrict__ h,
                    const int* __restrict__ batch_id, int n_nodes)
{
    __shared__ float sum_s[NB * C], sq_s[NB * C], cnt_s[NB];
    __shared__ int batch_s[RNPB];
    const int tid = threadIdx.x, w = tid >> 5, lane = tid & 31;
    const int rs = lane >> 3;          // row slot 0..3
    const int cg = lane & 7;           // 4-channel group
    const int base = blockIdx.x * RNPB;
    const int nvalid = min(RNPB, n_nodes - base);
    if (tid < NB * C) { sum_s[tid] = 0.f; sq_s[tid] = 0.f; }
    if (tid < NB) cnt_s[tid] = 0.f;
    if (tid < nvalid) batch_s[tid] = batch_id[base + tid];
    __syncthreads();
    if (tid < nvalid) atomicAdd(&cnt_s[batch_s[tid]], 1.0f);

    const int row0 = w * 32 + rs * 8;
    float4 ls = make_float4(0.f, 0.f, 0.f, 0.f);
    float4 lq = make_float4(0.f, 0.f, 0.f, 0.f);
    int curb = -1;
#pragma unroll
    for (int j = 0; j < 8; j++) {
        const int r = row0 + j;
        if (r < nvalid) {
            const int b = batch_s[r];
            if (b != curb) {
                if (curb >= 0) {
                    float* su = &sum_s[curb * C + cg * 4];
                    float* sq = &sq_s[curb * C + cg * 4];
                    atomicAdd(su + 0, ls.x); atomicAdd(su + 1, ls.y);
                    atomicAdd(su + 2, ls.z); atomicAdd(su + 3, ls.w);
                    atomicAdd(sq + 0, lq.x); atomicAdd(sq + 1, lq.y);
                    atomicAdd(sq + 2, lq.z); atomicAdd(sq + 3, lq.w);
                    ls = make_float4(0.f, 0.f, 0.f, 0.f);
                    lq = make_float4(0.f, 0.f, 0.f, 0.f);
                }
                curb = b;
            }
            float4 v = *reinterpret_cast<const float4*>(h + (size_t)(base + r) * C + cg * 4);
            ls.x += v.x; lq.x = fmaf(v.x, v.x, lq.x);
            ls.y += v.y; lq.y = fmaf(v.y, v.y, lq.y);
            ls.z += v.z; lq.z = fmaf(v.z, v.z, lq.z);
            ls.w += v.w; lq.w = fmaf(v.w, v.w, lq.w);
        }
    }
    {
        const int curb0 = __shfl_sync(0xffffffffu, curb, 0);
        const bool uniform = __all_sync(0xffffffffu, curb == curb0) && (curb0 >= 0);
        if (uniform) {
#pragma unroll
            for (int off = 8; off <= 16; off <<= 1) {
                ls.x += __shfl_xor_sync(0xffffffffu, ls.x, off);
                ls.y += __shfl_xor_sync(0xffffffffu, ls.y, off);
                ls.z += __shfl_xor_sync(0xffffffffu, ls.z, off);
                ls.w += __shfl_xor_sync(0xffffffffu, ls.w, off);
                lq.x += __shfl_xor_sync(0xffffffffu, lq.x, off);
                lq.y += __shfl_xor_sync(0xffffffffu, lq.y, off);
                lq.z += __shfl_xor_sync(0xffffffffu, lq.z, off);
                lq.w += __shfl_xor_sync(0xffffffffu, lq.w, off);
            }
            if (rs == 0) {
                float* su = &sum_s[curb0 * C + cg * 4];
                float* sq = &sq_s[curb0 * C + cg * 4];
                atomicAdd(su + 0, ls.x); atomicAdd(su + 1, ls.y);
                atomicAdd(su + 2, ls.z); atomicAdd(su + 3, ls.w);
                atomicAdd(sq + 0, lq.x); atomicAdd(sq + 1, lq.y);
                atomicAdd(sq + 2, lq.z); atomicAdd(sq + 3, lq.w);
            }
        } else if (curb >= 0) {
            float* su = &sum_s[curb * C + cg * 4];
            float* sq = &sq_s[curb * C + cg * 4];
            atomicAdd(su + 0, ls.x); atomicAdd(su + 1, ls.y);
            atomicAdd(su + 2, ls.z); atomicAdd(su + 3, ls.w);
            atomicAdd(sq + 0, lq.x); atomicAdd(sq + 1, lq.y);
            atomicAdd(sq + 2, lq.z); atomicAdd(sq + 3, lq.w);
        }
    }
    __syncthreads();
    if (tid < NB * C) { atomicAdd(&g_sum[tid], sum_s[tid]); atomicAdd(&g_sumsq[tid], sq_s[tid]); }
    if (tid < NB) atomicAdd(&g_cnt[tid], cnt_s[tid]);
}

__global__ void stats_kernel(const float* __restrict__ gamma,
                             const float* __restrict__ beta)
{
    int t = threadIdx.x;              // 256 = NB*C
    int b = t >> 5, c = t & 31, g = c >> 2;
    float cnt = g_cnt[b];
    float inv_cnt = 1.f / (cnt * 4.f + GEPS);   // C/G = 4
    float s = 0.f, qq = 0.f;
#pragma unroll
    for (int j = 0; j < 4; j++) {
        s += g_sum[b * C + g * 4 + j];
        qq += g_sumsq[b * C + g * 4 + j];
    }
    float mean = s * inv_cnt;
    float var = (qq - 2.f * mean * s + 4.f * cnt * mean * mean) * inv_cnt;
    float inv_std = rsqrtf(var + GEPS);
    float ga = gamma[c] * inv_std;
    g_scale[t] = ga;
    g_shift[t] = beta[c] - mean * ga;
}

__global__ void norm_relu_kernel(float* __restrict__ h,
                                 const int* __restrict__ batch_id,
                                 int n_nodes)
{
    int idx = blockIdx.x * blockDim.x + threadIdx.x;
    int total = n_nodes * (C / 4);
    if (idx >= total) return;
    int n = idx >> 3, s = idx & 7;
    int b = batch_id[n];
    float4 hv = reinterpret_cast<float4*>(h)[idx];
    float4 sc = reinterpret_cast<const float4*>(g_scale)[b * 8 + s];
    float4 sh = reinterpret_cast<const float4*>(g_shift)[b * 8 + s];
    float4 o;
    o.x = fmaxf(fmaf(hv.x, sc.x, sh.x), 0.f);
    o.y = fmaxf(fmaf(hv.y, sc.y, sh.y), 0.f);
    o.z = fmaxf(fmaf(hv.z, sc.z, sh.z), 0.f);
    o.w = fmaxf(fmaf(hv.w, sc.w, sh.w), 0.f);
    reinterpret_cast<float4*>(h)[idx] = o;
}

// ===================== launch =====================
extern "C" void kernel_launch(void* const* d_in, const int* in_sizes, int n_in,
                              void* d_out, int out_size)
{
    const float* data     = (const float*)d_in[0];
    const float* weights  = (const float*)d_in[1];
    const float* gamma    = (const float*)d_in[2];
    const float* beta     = (const float*)d_in[3];
    const int*   neigh    = (const int*)d_in[4];
    const int*   batch_id = (const int*)d_in[5];
    float* out = (float*)d_out;

    const int n_nodes = in_sizes[0] / C;
    const int n_tiles = (n_nodes + TILE_M - 1) / TILE_M;

    cudaFuncSetAttribute(deconv_kernel,
                         cudaFuncAttributeMaxDynamicSharedMemorySize, SMEM_TOTAL);

    zero_stats_kernel<<<1, 512>>>();
    convert_kernel<<<(n_nodes * 4 + 255) / 256, 256>>>(data, n_nodes);

    int grid = n_tiles < 296 ? n_tiles : 296;   // 2 CTAs/SM
    deconv_kernel<<<grid, THREADS, SMEM_TOTAL>>>(weights, neigh, out,
                                                 n_nodes, n_tiles);

    int gridR = (n_nodes + RNPB - 1) / RNPB;
    reduce_stats_kernel<<<gridR, 256>>>(out, batch_id, n_nodes);
    stats_kernel<<<1, NB * C>>>(gamma, beta);
    int total4 = n_nodes * (C / 4);
    norm_relu_kernel<<<(total4 + 255) / 256, 256>>>(out, batch_id, n_nodes);
}

// round 16
// speedup vs baseline: 1.2749x; 1.1040x over previous
#include <cuda_runtime.h>
#include <cuda_fp16.h>
#include <cstdint>

#define KTAPS 27
#define C 32
#define NB 8
#define TILE_M 256
#define THREADS 256
#define GEPS 1e-5f
#define MAXN 300032

// ---- dynamic SMEM layout ----
#define OFF_WF  0                   // 27*4*32*16 = 55296 (fragment-ordered W, fp16)
#define OFF_NG  55296               // 256*27*4 = 27648 (neighbor indices)
#define SMEM_TOTAL 82944

// ---- device-global scratch / accumulators ----
__device__ __half g_hdata[(size_t)MAXN * C];   // K-permuted fp16 copy of data
__device__ __align__(16) float g_sum[NB * C];
__device__ __align__(16) float g_sumsq[NB * C];
__device__ float g_cnt[NB];
__device__ __align__(16) float g_scale[NB * C];
__device__ __align__(16) float g_shift[NB * C];

// ===================== helpers =====================
__device__ __forceinline__ void mma16(float c[4], uint32_t a0, uint32_t a1,
                                      uint32_t a2, uint32_t a3,
                                      uint32_t b0, uint32_t b1) {
    asm volatile("mma.sync.aligned.m16n8k16.row.col.f32.f16.f16.f32 "
        "{%0,%1,%2,%3}, {%4,%5,%6,%7}, {%8,%9}, {%0,%1,%2,%3};"
        : "+f"(c[0]), "+f"(c[1]), "+f"(c[2]), "+f"(c[3])
        : "r"(a0), "r"(a1), "r"(a2), "r"(a3), "r"(b0), "r"(b1));
}
__device__ __forceinline__ uint32_t pack_h2(float lo, float hi) {
    __half2 h = __floats2half2_rn(lo, hi);
    return *reinterpret_cast<uint32_t*>(&h);
}

// ===================== kernels =====================
__global__ void zero_stats_kernel() {
    int t = threadIdx.x;
    if (t < NB * C) { g_sum[t] = 0.f; g_sumsq[t] = 0.f; }
    if (t < NB) g_cnt[t] = 0.f;
}

// Vectorized K-permuted fp16 convert (validated R15 form).
__global__ void __launch_bounds__(256)
convert_kernel(const float* __restrict__ data, int n_nodes) {
    int t = blockIdx.x * blockDim.x + threadIdx.x;
    if (t >= n_nodes * 4) return;
    const int n = t >> 2, q = t & 3;
    const float2* src = reinterpret_cast<const float2*>(data + ((size_t)n << 5));
    float2 v0 = src[q];          // L = 2q, 2q+1
    float2 v1 = src[q + 4];      // L = 2q+8, 2q+9
    float2 v2 = src[q + 8];      // L = 2q+16, 2q+17
    float2 v3 = src[q + 12];     // L = 2q+24, 2q+25
    uint4 o;
    o.x = pack_h2(v0.x, v0.y);
    o.y = pack_h2(v1.x, v1.y);
    o.z = pack_h2(v2.x, v2.y);
    o.w = pack_h2(v3.x, v3.y);
    reinterpret_cast<uint4*>(g_hdata + ((size_t)n << 5))[q] = o;
}

// Persistent deconv: fp16 m16n8k16 (validated R11 form, byte-identical).
__global__ void __launch_bounds__(THREADS, 2)
deconv_kernel(const float* __restrict__ weights,
              const int*   __restrict__ neigh,
              float*       __restrict__ h_out,
              int n_nodes, int n_tiles)
{
    extern __shared__ __align__(16) char smem[];
    const int tid = threadIdx.x;
    const int warp = tid >> 5;
    const int lane = tid & 31;
    const int q = lane & 3;
    const int rbase = lane >> 2;

    // Build fragment-ordered W table.
    for (int e = tid; e < KTAPS * 4 * 32; e += THREADS) {
        int k = e >> 7, rem = e & 127;
        int gn = rem >> 5, l = rem & 31;
        int cc = l & 3, rr = l >> 2;
        int n = gn * 8 + rr;
        uint4 f;
        uint32_t* fc = reinterpret_cast<uint32_t*>(&f);
#pragma unroll
        for (int j = 0; j < 4; j++) {
            int g = j >> 1, hb = j & 1;
            int kl = g * 16 + 2 * cc + 8 * hb;
            fc[j] = pack_h2(weights[(k * 32 + kl) * 32 + n],
                            weights[(k * 32 + kl + 1) * 32 + n]);
        }
        *reinterpret_cast<uint4*>(smem + OFF_WF + e * 16) = f;
    }
    __syncthreads();

#define LOAD_A(buf, kk) do { \
    _Pragma("unroll") \
    for (int mb = 0; mb < 2; mb++) { \
        int lr0 = warp * 32 + mb * 16 + rbase; \
        int nb0 = 0, nb1 = 0; \
        if (lr0 < nvalid)     nb0 = *(const int*)(smem + OFF_NG + (lr0 * KTAPS + (kk)) * 4); \
        if (lr0 + 8 < nvalid) nb1 = *(const int*)(smem + OFF_NG + ((lr0 + 8) * KTAPS + (kk)) * 4); \
        fAr[buf][mb * 2 + 0] = reinterpret_cast<const uint4*>(g_hdata + ((size_t)nb0 << 5))[q]; \
        fAr[buf][mb * 2 + 1] = reinterpret_cast<const uint4*>(g_hdata + ((size_t)nb1 << 5))[q]; \
    } \
} while (0)

    for (int tile = blockIdx.x; tile < n_tiles; tile += gridDim.x) {
        const int base = tile * TILE_M;
        const int nvalid = min(TILE_M, n_nodes - base);

        __syncthreads();
        for (int idx = tid; idx < nvalid * KTAPS; idx += THREADS)
            *(int*)(smem + OFF_NG + idx * 4) = neigh[(size_t)base * KTAPS + idx];
        __syncthreads();

        float acc[2][4][4];
#pragma unroll
        for (int mb = 0; mb < 2; mb++)
#pragma unroll
            for (int gn = 0; gn < 4; gn++)
#pragma unroll
                for (int p = 0; p < 4; p++) acc[mb][gn][p] = 0.f;

        uint4 fAr[2][4];
        LOAD_A(0, 0);

#pragma unroll
        for (int k = 0; k < KTAPS; k++) {
            const int cur = k & 1;
            if (k + 1 < KTAPS) LOAD_A((k + 1) & 1, k + 1);

            const char* wf = smem + OFF_WF + (size_t)(k * 4) * 512;
#pragma unroll
            for (int gn = 0; gn < 4; gn++) {
                uint4 Bf = *reinterpret_cast<const uint4*>(wf + gn * 512 + lane * 16);
#pragma unroll
                for (int mb = 0; mb < 2; mb++) {
                    const uint4 U0 = fAr[cur][mb * 2 + 0];
                    const uint4 U1 = fAr[cur][mb * 2 + 1];
                    mma16(acc[mb][gn], U0.x, U1.x, U0.y, U1.y, Bf.x, Bf.y);
                    mma16(acc[mb][gn], U0.z, U1.z, U0.w, U1.w, Bf.z, Bf.w);
                }
            }
        }

#pragma unroll
        for (int mb = 0; mb < 2; mb++) {
            const int r0 = base + warp * 32 + mb * 16 + (lane >> 2);
            const int r1 = r0 + 8;
#pragma unroll
            for (int gn = 0; gn < 4; gn++) {
                const int cc = gn * 8 + 2 * (lane & 3);
                if (r0 < n_nodes)
                    *(float2*)(h_out + (size_t)r0 * C + cc) =
                        make_float2(acc[mb][gn][0], acc[mb][gn][1]);
                if (r1 < n_nodes)
                    *(float2*)(h_out + (size_t)r1 * C + cc) =
                        make_float2(acc[mb][gn][2], acc[mb][gn][3]);
            }
        }
    }
#undef LOAD_A
}

// Per-(batch,channel) stats with a block-uniform fast path: single-batch full
// blocks (~99.4%) take a branch-free accumulate + shuffle-tree flush (bitwise
// identical partials to R15's uniform path); others fall back to the exact
// R15 run-detection body.
#define RNPB 256
__global__ void __launch_bounds__(256)
reduce_stats_kernel(const float* __restrict__ h,
                    const int* __restrict__ batch_id, int n_nodes)
{
    __shared__ float sum_s[NB * C], sq_s[NB * C], cnt_s[NB];
    __shared__ int batch_s[RNPB];
    const int tid = threadIdx.x, w = tid >> 5, lane = tid & 31;
    const int rs = lane >> 3;          // row slot 0..3
    const int cg = lane & 7;           // 4-channel group
    const int base = blockIdx.x * RNPB;
    const int nvalid = min(RNPB, n_nodes - base);
    if (tid < NB * C) { sum_s[tid] = 0.f; sq_s[tid] = 0.f; }
    if (tid < NB) cnt_s[tid] = 0.f;
    if (tid < nvalid) batch_s[tid] = batch_id[base + tid];
    __syncthreads();

    const int row0 = w * 32 + rs * 8;
    float4 ls = make_float4(0.f, 0.f, 0.f, 0.f);
    float4 lq = make_float4(0.f, 0.f, 0.f, 0.f);

    if (nvalid == RNPB && batch_s[0] == batch_s[RNPB - 1]) {
        // ---- fast path: whole block is one batch ----
        const int b0 = batch_s[0];
        if (tid == 0) atomicAdd(&cnt_s[b0], (float)RNPB);
#pragma unroll
        for (int j = 0; j < 8; j++) {
            float4 v = *reinterpret_cast<const float4*>(
                h + (size_t)(base + row0 + j) * C + cg * 4);
            ls.x += v.x; lq.x = fmaf(v.x, v.x, lq.x);
            ls.y += v.y; lq.y = fmaf(v.y, v.y, lq.y);
            ls.z += v.z; lq.z = fmaf(v.z, v.z, lq.z);
            ls.w += v.w; lq.w = fmaf(v.w, v.w, lq.w);
        }
#pragma unroll
        for (int off = 8; off <= 16; off <<= 1) {
            ls.x += __shfl_xor_sync(0xffffffffu, ls.x, off);
            ls.y += __shfl_xor_sync(0xffffffffu, ls.y, off);
            ls.z += __shfl_xor_sync(0xffffffffu, ls.z, off);
            ls.w += __shfl_xor_sync(0xffffffffu, ls.w, off);
            lq.x += __shfl_xor_sync(0xffffffffu, lq.x, off);
            lq.y += __shfl_xor_sync(0xffffffffu, lq.y, off);
            lq.z += __shfl_xor_sync(0xffffffffu, lq.z, off);
            lq.w += __shfl_xor_sync(0xffffffffu, lq.w, off);
        }
        if (rs == 0) {
            float* su = &sum_s[b0 * C + cg * 4];
            float* sq = &sq_s[b0 * C + cg * 4];
            atomicAdd(su + 0, ls.x); atomicAdd(su + 1, ls.y);
            atomicAdd(su + 2, ls.z); atomicAdd(su + 3, ls.w);
            atomicAdd(sq + 0, lq.x); atomicAdd(sq + 1, lq.y);
            atomicAdd(sq + 2, lq.z); atomicAdd(sq + 3, lq.w);
        }
    } else {
        // ---- slow path: exact R15 run-detection body ----
        if (tid < nvalid) atomicAdd(&cnt_s[batch_s[tid]], 1.0f);
        int curb = -1;
#pragma unroll
        for (int j = 0; j < 8; j++) {
            const int r = row0 + j;
            if (r < nvalid) {
                const int b = batch_s[r];
                if (b != curb) {
                    if (curb >= 0) {
                        float* su = &sum_s[curb * C + cg * 4];
                        float* sq = &sq_s[curb * C + cg * 4];
                        atomicAdd(su + 0, ls.x); atomicAdd(su + 1, ls.y);
                        atomicAdd(su + 2, ls.z); atomicAdd(su + 3, ls.w);
                        atomicAdd(sq + 0, lq.x); atomicAdd(sq + 1, lq.y);
                        atomicAdd(sq + 2, lq.z); atomicAdd(sq + 3, lq.w);
                        ls = make_float4(0.f, 0.f, 0.f, 0.f);
                        lq = make_float4(0.f, 0.f, 0.f, 0.f);
                    }
                    curb = b;
                }
                float4 v = *reinterpret_cast<const float4*>(
                    h + (size_t)(base + r) * C + cg * 4);
                ls.x += v.x; lq.x = fmaf(v.x, v.x, lq.x);
                ls.y += v.y; lq.y = fmaf(v.y, v.y, lq.y);
                ls.z += v.z; lq.z = fmaf(v.z, v.z, lq.z);
                ls.w += v.w; lq.w = fmaf(v.w, v.w, lq.w);
            }
        }
        if (curb >= 0) {
            float* su = &sum_s[curb * C + cg * 4];
            float* sq = &sq_s[curb * C + cg * 4];
            atomicAdd(su + 0, ls.x); atomicAdd(su + 1, ls.y);
            atomicAdd(su + 2, ls.z); atomicAdd(su + 3, ls.w);
            atomicAdd(sq + 0, lq.x); atomicAdd(sq + 1, lq.y);
            atomicAdd(sq + 2, lq.z); atomicAdd(sq + 3, lq.w);
        }
    }
    __syncthreads();
    if (tid < NB * C) { atomicAdd(&g_sum[tid], sum_s[tid]); atomicAdd(&g_sumsq[tid], sq_s[tid]); }
    if (tid < NB) atomicAdd(&g_cnt[tid], cnt_s[tid]);
}

__global__ void stats_kernel(const float* __restrict__ gamma,
                             const float* __restrict__ beta)
{
    int t = threadIdx.x;              // 256 = NB*C
    int b = t >> 5, c = t & 31, g = c >> 2;
    float cnt = g_cnt[b];
    float inv_cnt = 1.f / (cnt * 4.f + GEPS);   // C/G = 4
    float s = 0.f, qq = 0.f;
#pragma unroll
    for (int j = 0; j < 4; j++) {
        s += g_sum[b * C + g * 4 + j];
        qq += g_sumsq[b * C + g * 4 + j];
    }
    float mean = s * inv_cnt;
    float var = (qq - 2.f * mean * s + 4.f * cnt * mean * mean) * inv_cnt;
    float inv_std = rsqrtf(var + GEPS);
    float ga = gamma[c] * inv_std;
    g_scale[t] = ga;
    g_shift[t] = beta[c] - mean * ga;
}

__global__ void norm_relu_kernel(float* __restrict__ h,
                                 const int* __restrict__ batch_id,
                                 int n_nodes)
{
    int idx = blockIdx.x * blockDim.x + threadIdx.x;
    int total = n_nodes * (C / 4);
    if (idx >= total) return;
    int n = idx >> 3, s = idx & 7;
    int b = batch_id[n];
    float4 hv = reinterpret_cast<float4*>(h)[idx];
    float4 sc = reinterpret_cast<const float4*>(g_scale)[b * 8 + s];
    float4 sh = reinterpret_cast<const float4*>(g_shift)[b * 8 + s];
    float4 o;
    o.x = fmaxf(fmaf(hv.x, sc.x, sh.x), 0.f);
    o.y = fmaxf(fmaf(hv.y, sc.y, sh.y), 0.f);
    o.z = fmaxf(fmaf(hv.z, sc.z, sh.z), 0.f);
    o.w = fmaxf(fmaf(hv.w, sc.w, sh.w), 0.f);
    reinterpret_cast<float4*>(h)[idx] = o;
}

// ===================== launch =====================
extern "C" void kernel_launch(void* const* d_in, const int* in_sizes, int n_in,
                              void* d_out, int out_size)
{
    const float* data     = (const float*)d_in[0];
    const float* weights  = (const float*)d_in[1];
    const float* gamma    = (const float*)d_in[2];
    const float* beta     = (const float*)d_in[3];
    const int*   neigh    = (const int*)d_in[4];
    const int*   batch_id = (const int*)d_in[5];
    float* out = (float*)d_out;

    const int n_nodes = in_sizes[0] / C;
    const int n_tiles = (n_nodes + TILE_M - 1) / TILE_M;

    cudaFuncSetAttribute(deconv_kernel,
                         cudaFuncAttributeMaxDynamicSharedMemorySize, SMEM_TOTAL);

    zero_stats_kernel<<<1, 512>>>();
    convert_kernel<<<(n_nodes * 4 + 255) / 256, 256>>>(data, n_nodes);

    int grid = n_tiles < 296 ? n_tiles : 296;   // 2 CTAs/SM
    deconv_kernel<<<grid, THREADS, SMEM_TOTAL>>>(weights, neigh, out,
                                                 n_nodes, n_tiles);

    int gridR = (n_nodes + RNPB - 1) / RNPB;
    reduce_stats_kernel<<<gridR, 256>>>(out, batch_id, n_nodes);
    stats_kernel<<<1, NB * C>>>(gamma, beta);
    int total4 = n_nodes * (C / 4);
    norm_relu_kernel<<<(total4 + 255) / 256, 256>>>(out, batch_id, n_nodes);
}